// round 5
// baseline (speedup 1.0000x reference)
#include <cuda_runtime.h>
#include <cstdint>
#include <math.h>

// Problem constants (fixed by the dataset)
#define BB 8
#define HH 64
#define WW 64
#define CC 256
#define FF 256
#define NPIX (BB*HH*WW)   // 32768
#define KTOT 2304         // 9*256

__device__ float g_om[NPIX * 27];
__device__ uint32_t g_Wt[FF * KTOT];   // [256][2304]  Wt[f][k] = tf32(W[k][f])

// ============================ helpers ============================
__device__ __forceinline__ uint32_t smem_u32(const void* p) {
    uint32_t a;
    asm("{ .reg .u64 t; cvta.to.shared.u64 t, %1; cvt.u32.u64 %0, t; }"
        : "=r"(a) : "l"(p));
    return a;
}
__device__ __forceinline__ uint32_t f2tf32(float f) {
    uint32_t o;
    asm("cvt.rna.tf32.f32 %0, %1;" : "=r"(o) : "f"(f));
    return o;
}
#define CP_ASYNC16(dst, src) \
    asm volatile("cp.async.cg.shared.global [%0], [%1], 16;" :: "r"(dst), "l"(src) : "memory")
#define CP_COMMIT() asm volatile("cp.async.commit_group;" ::: "memory")
#define CP_WAIT0()  asm volatile("cp.async.wait_group 0;" ::: "memory")

#define BAR_SYNC(id, cnt) \
    asm volatile("bar.sync %0, %1;" :: "r"(id), "r"(cnt) : "memory")
#define BAR_ARRIVE(id, cnt) \
    asm volatile("bar.arrive %0, %1;" :: "r"(id), "r"(cnt) : "memory")

#define LDSM4(r, a) \
    asm volatile("ldmatrix.sync.aligned.m8n8.x4.shared.b16 {%0,%1,%2,%3}, [%4];" \
        : "=r"((r)[0]), "=r"((r)[1]), "=r"((r)[2]), "=r"((r)[3]) : "r"(a))
#define LDSM2(r, a) \
    asm volatile("ldmatrix.sync.aligned.m8n8.x2.shared.b16 {%0,%1}, [%2];" \
        : "=r"((r)[0]), "=r"((r)[1]) : "r"(a))

__device__ __forceinline__ void mma_tf32(float* c, const uint32_t* a, const uint32_t* b) {
    asm volatile("mma.sync.aligned.m16n8k8.row.col.f32.tf32.tf32.f32 "
        "{%0,%1,%2,%3}, {%4,%5,%6,%7}, {%8,%9}, {%0,%1,%2,%3};"
        : "+f"(c[0]), "+f"(c[1]), "+f"(c[2]), "+f"(c[3])
        : "r"(a[0]), "r"(a[1]), "r"(a[2]), "r"(a[3]), "r"(b[0]), "r"(b[1]));
}

// ============================ Kernel 0: W transpose + tf32 round ==============
__global__ __launch_bounds__(256) void transpose_w(const float* __restrict__ W) {
    __shared__ float t[32][33];
    int k0 = blockIdx.x * 32, f0 = blockIdx.y * 32;
    int tx = threadIdx.x & 31, ty = threadIdx.x >> 5;
    #pragma unroll
    for (int r = 0; r < 32; r += 8)
        t[ty + r][tx] = W[(k0 + ty + r) * 256 + f0 + tx];
    __syncthreads();
    #pragma unroll
    for (int r = 0; r < 32; r += 8)
        g_Wt[(f0 + ty + r) * KTOT + k0 + tx] = f2tf32(t[tx][ty + r]);
}

// ============================ Kernel 1: offset/mask conv (fp32) ==============
__global__ __launch_bounds__(256) void om_conv_kernel(
    const float* __restrict__ x, const float* __restrict__ omw,
    const float* __restrict__ omb)
{
    __shared__ float ws[256 * 32];
    const int bid = blockIdx.x;
    const int xh = bid & 1;
    const int y = (bid >> 1) & 63;
    const int b = bid >> 7;
    const int x0 = xh * 32;
    const int tid = threadIdx.x;
    const int p = tid >> 3;
    const int fg = tid & 7;

    for (int i = tid; i < 256 * 32; i += 256) ws[i] = 0.f;

    float4 acc = make_float4(0.f, 0.f, 0.f, 0.f);
    const int gx = x0 + p;

    for (int tap = 0; tap < 9; ++tap) {
        __syncthreads();
        for (int i = tid; i < 256 * 27; i += 256) {
            int c = i / 27;
            int f = i - c * 27;
            ws[c * 32 + f] = omw[(tap * 256 + c) * 27 + f];
        }
        __syncthreads();
        const int dy = tap / 3;
        const int dx = tap - dy * 3;
        const int sy = y - 1 + dy;
        const int sx = gx - 1 + dx;
        if ((unsigned)sy < 64u && (unsigned)sx < 64u) {
            const float* xr = x + (((b * 64 + sy) * 64) + sx) * 256;
            #pragma unroll 4
            for (int c4 = 0; c4 < 64; ++c4) {
                float4 xv = *(const float4*)(xr + c4 * 4);
                const float* wp = &ws[(c4 * 4) * 32 + fg * 4];
                float4 w0 = *(const float4*)(wp);
                float4 w1 = *(const float4*)(wp + 32);
                float4 w2 = *(const float4*)(wp + 64);
                float4 w3 = *(const float4*)(wp + 96);
                acc.x = fmaf(xv.x, w0.x, acc.x); acc.y = fmaf(xv.x, w0.y, acc.y);
                acc.z = fmaf(xv.x, w0.z, acc.z); acc.w = fmaf(xv.x, w0.w, acc.w);
                acc.x = fmaf(xv.y, w1.x, acc.x); acc.y = fmaf(xv.y, w1.y, acc.y);
                acc.z = fmaf(xv.y, w1.z, acc.z); acc.w = fmaf(xv.y, w1.w, acc.w);
                acc.x = fmaf(xv.z, w2.x, acc.x); acc.y = fmaf(xv.z, w2.y, acc.y);
                acc.z = fmaf(xv.z, w2.z, acc.z); acc.w = fmaf(xv.z, w2.w, acc.w);
                acc.x = fmaf(xv.w, w3.x, acc.x); acc.y = fmaf(xv.w, w3.y, acc.y);
                acc.z = fmaf(xv.w, w3.z, acc.z); acc.w = fmaf(xv.w, w3.w, acc.w);
            }
        }
    }
    const int pix = (b * 64 + y) * 64 + gx;
    float vals[4] = {acc.x, acc.y, acc.z, acc.w};
    #pragma unroll
    for (int ff = 0; ff < 4; ++ff) {
        int f = fg * 4 + ff;
        if (f < 27) {
            float v = vals[ff] + omb[f];
            if (f >= 18) v = 2.f / (1.f + expf(-v));
            g_om[pix * 27 + f] = v;
        }
    }
}

// ============================ Kernel 2: warp-specialized fused GEMM ===========
// CTA: 256 threads. Warps 0-3 = consumers (MMA), warps 4-7 = producers
// (sampling + B staging). Tile M=128 x N=128, grid 512 (256 m x 2 n).
// Consumer warp tile 64x64 (2m x 2n). 72 K-chunks of 32; 2 smem stages.
// Named barriers: full[s]=1+s, empty[s]=3+s (count 256), producer params=5 (128).
#define SM3_SW   0            // [2][128] float4 bilinear weights (4KB)
#define SM3_SO   4096         // [2][128] int4 corner offsets (4KB)
#define SM3_A    9216         // [2][128][32] tf32 (32KB), 1KB aligned
#define SM3_B    41984        // [2][128][32] tf32 (32KB), 1KB aligned
#define SM3_TOTAL 74752

__device__ __forceinline__ void compute_params3(int kp, int m, float4* sw4, int4* so4) {
    const float* omp = g_om + m * 27;
    const int y = (m >> 6) & 63, xc = m & 63, b = m >> 12;
    const int ky = kp / 3, kx = kp - ky * 3;
    float py = (float)(y - 1 + ky) + omp[2 * kp];
    float px = (float)(xc - 1 + kx) + omp[2 * kp + 1];
    float msk = omp[18 + kp];
    float y0f = floorf(py), x0f = floorf(px);
    float wy1 = py - y0f, wy0 = 1.f - wy1;
    float wx1 = px - x0f, wx0 = 1.f - wx1;
    int iy0 = (int)y0f, ix0 = (int)x0f;
    int iy1 = iy0 + 1, ix1 = ix0 + 1;
    bool vy0 = (unsigned)iy0 < 64u, vy1 = (unsigned)iy1 < 64u;
    bool vx0 = (unsigned)ix0 < 64u, vx1 = (unsigned)ix1 < 64u;
    int cy0 = min(max(iy0, 0), 63), cy1 = min(max(iy1, 0), 63);
    int cx0 = min(max(ix0, 0), 63), cx1 = min(max(ix1, 0), 63);
    int base = b << 12;
    int4 o;
    o.x = (base + cy0 * 64 + cx0) << 8;
    o.y = (base + cy0 * 64 + cx1) << 8;
    o.z = (base + cy1 * 64 + cx0) << 8;
    o.w = (base + cy1 * 64 + cx1) << 8;
    float4 w;
    w.x = (vy0 && vx0) ? wy0 * wx0 * msk : 0.f;
    w.y = (vy0 && vx1) ? wy0 * wx1 * msk : 0.f;
    w.z = (vy1 && vx0) ? wy1 * wx0 * msk : 0.f;
    w.w = (vy1 && vx1) ? wy1 * wx1 * msk : 0.f;
    *so4 = o;
    *sw4 = w;
}

// Producer sampling: 4 producer warps, 8 lanes/pixel, lane owns 4 channels,
// loads all 4 corners itself -> every LDG.128 covers 4 dense 128B lines.
__device__ __forceinline__ void sample3(const float* __restrict__ x,
                                        char* smem, int j, int stage,
                                        int pw, int lane) {
    const int pb = (j >> 3) & 1;
    const float4* SW = (const float4*)(smem + SM3_SW) + pb * 128;
    const int4*   SO = (const int4*)(smem + SM3_SO) + pb * 128;
    uint32_t* A = (uint32_t*)(smem + SM3_A + stage * 16384);
    const int l = lane & 7, pq = lane >> 3;
    const int cbase = (j & 7) * 32 + l * 4;
    #pragma unroll
    for (int it = 0; it < 8; ++it) {
        const int px = pw * 32 + it * 4 + pq;
        const float4 w = SW[px];
        const int4 o = SO[px];
        float4 v00 = *(const float4*)(x + o.x + cbase);
        float4 v01 = *(const float4*)(x + o.y + cbase);
        float4 v10 = *(const float4*)(x + o.z + cbase);
        float4 v11 = *(const float4*)(x + o.w + cbase);
        uint4 r;
        r.x = f2tf32(w.x * v00.x + w.y * v01.x + w.z * v10.x + w.w * v11.x);
        r.y = f2tf32(w.x * v00.y + w.y * v01.y + w.z * v10.y + w.w * v11.y);
        r.z = f2tf32(w.x * v00.z + w.y * v01.z + w.z * v10.z + w.w * v11.z);
        r.w = f2tf32(w.x * v00.w + w.y * v01.w + w.z * v10.w + w.w * v11.w);
        const int gran = l ^ (px & 7);
        *(uint4*)(A + px * 32 + gran * 4) = r;
    }
}

// Stage B chunk j (128 n-major rows x 128B), XOR swizzle; pt = producer tid 0..127.
__device__ __forceinline__ void loadB3(uint32_t sb, int f0, int j, int stage, int pt) {
    const uint32_t dbase = sb + SM3_B + stage * 16384 + pt * 128;
    const uint32_t* src = g_Wt + (size_t)(f0 + pt) * KTOT + j * 32;
    #pragma unroll
    for (int g = 0; g < 8; ++g)
        CP_ASYNC16(dbase + ((g ^ (pt & 7)) * 16), src + g * 4);
}

__global__ __launch_bounds__(256, 1) void dcn_mma_kernel(
    const float* __restrict__ x,      // [8,64,64,256]
    const float* __restrict__ bias,   // [256]
    float* __restrict__ out)          // [32768,256]
{
    extern __shared__ char smem[];
    const uint32_t sb = smem_u32(smem);
    const int tid = threadIdx.x;
    const int lane = tid & 31, wid = tid >> 5;
    const int m0 = (blockIdx.x >> 1) * 128;
    const int f0 = (blockIdx.x & 1) * 128;

    if (wid >= 4) {
        // =================== PRODUCER ===================
        const int pt = tid - 128;        // 0..127
        const int pw = wid - 4;          // 0..3
        float4* SW0 = (float4*)(smem + SM3_SW);
        int4*   SO0 = (int4*)(smem + SM3_SO);

        for (int j = 0; j < 72; ++j) {
            const int s = j & 1;
            if ((j & 7) == 0) {
                const int kp = j >> 3, pb = kp & 1;
                compute_params3(kp, m0 + pt, SW0 + pb * 128 + pt, SO0 + pb * 128 + pt);
                BAR_SYNC(5, 128);
            }
            if (j >= 2) BAR_SYNC(3 + s, 256);   // wait empty[s]
            loadB3(sb, f0, j, s, pt);
            CP_COMMIT();
            sample3(x, smem, j, s, pw, lane);
            CP_WAIT0();
            BAR_ARRIVE(1 + s, 256);             // signal full[s]
        }
    } else {
        // =================== CONSUMER ===================
        const int g = lane >> 2, cq = lane & 3;
        const int wm = wid & 1, wn = wid >> 1;

        float acc[4][8][4];
        #pragma unroll
        for (int mt = 0; mt < 4; ++mt)
            #pragma unroll
            for (int nt = 0; nt < 8; ++nt)
                #pragma unroll
                for (int q = 0; q < 4; ++q) acc[mt][nt][q] = 0.f;

        const int rowA = wm * 64 + (lane & 15);
        const int hiA = (lane >> 4) & 1;
        uint32_t koffA[4], koffB[4];
        #pragma unroll
        for (int ks = 0; ks < 4; ++ks) {
            koffA[ks] = (uint32_t)((ks * 32 + hiA * 16) ^ ((rowA & 7) * 16));
            koffB[ks] = (uint32_t)((ks * 32 + ((lane >> 3) & 1) * 16) ^ ((lane & 7) * 16));
        }
        const uint32_t rowAoff = (uint32_t)(rowA * 128);
        const uint32_t rowBoff = (uint32_t)((wn * 64 + (lane & 7)) * 128);

        for (int j = 0; j < 72; ++j) {
            const int s = j & 1;
            BAR_SYNC(1 + s, 256);               // wait full[s]
            const uint32_t Ab = sb + SM3_A + s * 16384 + rowAoff;
            const uint32_t Bb = sb + SM3_B + s * 16384 + rowBoff;
            #pragma unroll
            for (int ks = 0; ks < 4; ++ks) {
                uint32_t a[4][4];
                #pragma unroll
                for (int mt = 0; mt < 4; ++mt)
                    LDSM4(a[mt], Ab + mt * 2048 + koffA[ks]);
                #pragma unroll
                for (int nt = 0; nt < 8; ++nt) {
                    uint32_t b[2];
                    LDSM2(b, Bb + nt * 1024 + koffB[ks]);
                    #pragma unroll
                    for (int mt = 0; mt < 4; ++mt)
                        mma_tf32(acc[mt][nt], a[mt], b);
                }
            }
            BAR_ARRIVE(3 + s, 256);             // signal empty[s]
        }

        // Epilogue: bias + store
        #pragma unroll
        for (int nt = 0; nt < 8; ++nt) {
            const int fl = f0 + wn * 64 + nt * 8 + 2 * cq;
            const float2 bv = *(const float2*)(bias + fl);
            #pragma unroll
            for (int mt = 0; mt < 4; ++mt) {
                const int r0 = m0 + wm * 64 + mt * 16 + g;
                float2 v0, v1;
                v0.x = acc[mt][nt][0] + bv.x;
                v0.y = acc[mt][nt][1] + bv.y;
                v1.x = acc[mt][nt][2] + bv.x;
                v1.y = acc[mt][nt][3] + bv.y;
                *(float2*)(out + (size_t)r0 * 256 + fl) = v0;
                *(float2*)(out + (size_t)(r0 + 8) * 256 + fl) = v1;
            }
        }
    }
}

// ============================ Launch ============================
extern "C" void kernel_launch(void* const* d_in, const int* in_sizes, int n_in,
                              void* d_out, int out_size) {
    (void)in_sizes; (void)n_in; (void)out_size;
    const float* x    = (const float*)d_in[0];
    const float* omw  = (const float*)d_in[1];
    const float* omb  = (const float*)d_in[2];
    const float* W    = (const float*)d_in[3];
    const float* bias = (const float*)d_in[4];
    float* out = (float*)d_out;

    static bool attr_set = false;
    if (!attr_set) {
        cudaFuncSetAttribute(dcn_mma_kernel,
                             cudaFuncAttributeMaxDynamicSharedMemorySize, SM3_TOTAL);
        attr_set = true;
    }

    transpose_w<<<dim3(KTOT / 32, FF / 32), 256>>>(W);
    om_conv_kernel<<<1024, 256>>>(x, omw, omb);
    dcn_mma_kernel<<<512, 256, SM3_TOTAL>>>(x, bias, out);
}

// round 6
// speedup vs baseline: 1.4216x; 1.4216x over previous
#include <cuda_runtime.h>
#include <cstdint>
#include <math.h>

// Problem constants (fixed by the dataset)
#define BB 8
#define HH 64
#define WW 64
#define CC 256
#define FF 256
#define NPIX (BB*HH*WW)   // 32768
#define KTOT 2304         // 9*256

__device__ float g_om[NPIX * 27];
__device__ uint32_t g_Wt[FF * KTOT];   // [256][2304]  Wt[f][k] = tf32(W[k][f])

// ============================ helpers ============================
__device__ __forceinline__ uint32_t smem_u32(const void* p) {
    uint32_t a;
    asm("{ .reg .u64 t; cvta.to.shared.u64 t, %1; cvt.u32.u64 %0, t; }"
        : "=r"(a) : "l"(p));
    return a;
}
__device__ __forceinline__ uint32_t f2tf32(float f) {
    uint32_t o;
    asm("cvt.rna.tf32.f32 %0, %1;" : "=r"(o) : "f"(f));
    return o;
}
#define CP_ASYNC16(dst, src) \
    asm volatile("cp.async.cg.shared.global [%0], [%1], 16;" :: "r"(dst), "l"(src) : "memory")
#define CP_COMMIT() asm volatile("cp.async.commit_group;" ::: "memory")
#define CP_WAIT0()  asm volatile("cp.async.wait_group 0;" ::: "memory")

#define LDSM4(r, a) \
    asm volatile("ldmatrix.sync.aligned.m8n8.x4.shared.b16 {%0,%1,%2,%3}, [%4];" \
        : "=r"((r)[0]), "=r"((r)[1]), "=r"((r)[2]), "=r"((r)[3]) : "r"(a))

__device__ __forceinline__ void mma_tf32(float* c, const uint32_t* a, const uint32_t* b) {
    asm volatile("mma.sync.aligned.m16n8k8.row.col.f32.tf32.tf32.f32 "
        "{%0,%1,%2,%3}, {%4,%5,%6,%7}, {%8,%9}, {%0,%1,%2,%3};"
        : "+f"(c[0]), "+f"(c[1]), "+f"(c[2]), "+f"(c[3])
        : "r"(a[0]), "r"(a[1]), "r"(a[2]), "r"(a[3]), "r"(b[0]), "r"(b[1]));
}

// ============================ Kernel 0: W transpose + tf32 round ==============
__global__ __launch_bounds__(256) void transpose_w(const float* __restrict__ W) {
    __shared__ float t[32][33];
    int k0 = blockIdx.x * 32, f0 = blockIdx.y * 32;
    int tx = threadIdx.x & 31, ty = threadIdx.x >> 5;
    #pragma unroll
    for (int r = 0; r < 32; r += 8)
        t[ty + r][tx] = W[(k0 + ty + r) * 256 + f0 + tx];
    __syncthreads();
    #pragma unroll
    for (int r = 0; r < 32; r += 8)
        g_Wt[(f0 + ty + r) * KTOT + k0 + tx] = f2tf32(t[tx][ty + r]);
}

// ============================ Kernel 1: offset/mask conv (fp32) ==============
__global__ __launch_bounds__(256) void om_conv_kernel(
    const float* __restrict__ x, const float* __restrict__ omw,
    const float* __restrict__ omb)
{
    __shared__ float ws[256 * 32];
    const int bid = blockIdx.x;
    const int xh = bid & 1;
    const int y = (bid >> 1) & 63;
    const int b = bid >> 7;
    const int x0 = xh * 32;
    const int tid = threadIdx.x;
    const int p = tid >> 3;
    const int fg = tid & 7;

    for (int i = tid; i < 256 * 32; i += 256) ws[i] = 0.f;

    float4 acc = make_float4(0.f, 0.f, 0.f, 0.f);
    const int gx = x0 + p;

    for (int tap = 0; tap < 9; ++tap) {
        __syncthreads();
        for (int i = tid; i < 256 * 27; i += 256) {
            int c = i / 27;
            int f = i - c * 27;
            ws[c * 32 + f] = omw[(tap * 256 + c) * 27 + f];
        }
        __syncthreads();
        const int dy = tap / 3;
        const int dx = tap - dy * 3;
        const int sy = y - 1 + dy;
        const int sx = gx - 1 + dx;
        if ((unsigned)sy < 64u && (unsigned)sx < 64u) {
            const float* xr = x + (((b * 64 + sy) * 64) + sx) * 256;
            #pragma unroll 4
            for (int c4 = 0; c4 < 64; ++c4) {
                float4 xv = *(const float4*)(xr + c4 * 4);
                const float* wp = &ws[(c4 * 4) * 32 + fg * 4];
                float4 w0 = *(const float4*)(wp);
                float4 w1 = *(const float4*)(wp + 32);
                float4 w2 = *(const float4*)(wp + 64);
                float4 w3 = *(const float4*)(wp + 96);
                acc.x = fmaf(xv.x, w0.x, acc.x); acc.y = fmaf(xv.x, w0.y, acc.y);
                acc.z = fmaf(xv.x, w0.z, acc.z); acc.w = fmaf(xv.x, w0.w, acc.w);
                acc.x = fmaf(xv.y, w1.x, acc.x); acc.y = fmaf(xv.y, w1.y, acc.y);
                acc.z = fmaf(xv.y, w1.z, acc.z); acc.w = fmaf(xv.y, w1.w, acc.w);
                acc.x = fmaf(xv.z, w2.x, acc.x); acc.y = fmaf(xv.z, w2.y, acc.y);
                acc.z = fmaf(xv.z, w2.z, acc.z); acc.w = fmaf(xv.z, w2.w, acc.w);
                acc.x = fmaf(xv.w, w3.x, acc.x); acc.y = fmaf(xv.w, w3.y, acc.y);
                acc.z = fmaf(xv.w, w3.z, acc.z); acc.w = fmaf(xv.w, w3.w, acc.w);
            }
        }
    }
    const int pix = (b * 64 + y) * 64 + gx;
    float vals[4] = {acc.x, acc.y, acc.z, acc.w};
    #pragma unroll
    for (int ff = 0; ff < 4; ++ff) {
        int f = fg * 4 + ff;
        if (f < 27) {
            float v = vals[ff] + omb[f];
            if (f >= 18) v = 2.f / (1.f + expf(-v));
            g_om[pix * 27 + f] = v;
        }
    }
}

// ============================ Kernel 2: fused sampling + mma TF32 GEMM ========
// CTA: 256 threads (8 warps), tile M=256 x N=128. Grid 256 (128 m x 2 n).
// Warps: 4(m) x 2(n), warp tile 64x64, acc[4 mt][8 nt][4].
// 72 K-chunks of 32; 2 smem stages; gather for chunk j+1 is register-pipelined
// through the MMA stream of chunk j (LDG early, combine+STS between MMA blocks).
#define SM_SW 0              // [2][256] float4 bilinear weights (8KB)
#define SM_SO 8192           // [2][256] int4 corner offsets (8KB)
#define SM_A  16384          // [2][256][32] tf32 (64KB)
#define SM_B  81920          // [2][128][32] tf32 (32KB)
#define SM_TOTAL 114688

__device__ __forceinline__ void compute_params3(int kp, int m, float4* sw4, int4* so4) {
    const float* omp = g_om + m * 27;
    const int y = (m >> 6) & 63, xc = m & 63, b = m >> 12;
    const int ky = kp / 3, kx = kp - ky * 3;
    float py = (float)(y - 1 + ky) + omp[2 * kp];
    float px = (float)(xc - 1 + kx) + omp[2 * kp + 1];
    float msk = omp[18 + kp];
    float y0f = floorf(py), x0f = floorf(px);
    float wy1 = py - y0f, wy0 = 1.f - wy1;
    float wx1 = px - x0f, wx0 = 1.f - wx1;
    int iy0 = (int)y0f, ix0 = (int)x0f;
    int iy1 = iy0 + 1, ix1 = ix0 + 1;
    bool vy0 = (unsigned)iy0 < 64u, vy1 = (unsigned)iy1 < 64u;
    bool vx0 = (unsigned)ix0 < 64u, vx1 = (unsigned)ix1 < 64u;
    int cy0 = min(max(iy0, 0), 63), cy1 = min(max(iy1, 0), 63);
    int cx0 = min(max(ix0, 0), 63), cx1 = min(max(ix1, 0), 63);
    int base = b << 12;
    int4 o;
    o.x = (base + cy0 * 64 + cx0) << 8;
    o.y = (base + cy0 * 64 + cx1) << 8;
    o.z = (base + cy1 * 64 + cx0) << 8;
    o.w = (base + cy1 * 64 + cx1) << 8;
    float4 w;
    w.x = (vy0 && vx0) ? wy0 * wx0 * msk : 0.f;
    w.y = (vy0 && vx1) ? wy0 * wx1 * msk : 0.f;
    w.z = (vy1 && vx0) ? wy1 * wx0 * msk : 0.f;
    w.w = (vy1 && vx1) ? wy1 * wx1 * msk : 0.f;
    *so4 = o;
    *sw4 = w;
}

// Stage B chunk j (128 n-major rows x 128B), XOR swizzle; pt = tid (0..127 only).
__device__ __forceinline__ void loadB3(uint32_t sb, int f0, int j, int stage, int pt) {
    const uint32_t dbase = sb + SM_B + stage * 16384 + pt * 128;
    const uint32_t* src = g_Wt + (size_t)(f0 + pt) * KTOT + j * 32;
    #pragma unroll
    for (int g = 0; g < 8; ++g)
        CP_ASYNC16(dbase + ((g ^ (pt & 7)) * 16), src + g * 4);
}

struct GBuf { float4 v0, v1, v2, v3; };

__device__ __forceinline__ void gather_issue(const float* __restrict__ x,
                                             const int4* SOn, int px, int cb,
                                             GBuf& u) {
    const int4 o = SOn[px];
    u.v0 = *(const float4*)(x + o.x + cb);
    u.v1 = *(const float4*)(x + o.y + cb);
    u.v2 = *(const float4*)(x + o.z + cb);
    u.v3 = *(const float4*)(x + o.w + cb);
}

__device__ __forceinline__ void combine_sts(char* smem, const float4* SWn,
                                            int px, int l, uint32_t Ans_off,
                                            const GBuf& u) {
    const float4 w = SWn[px];
    uint4 r;
    r.x = f2tf32(w.x * u.v0.x + w.y * u.v1.x + w.z * u.v2.x + w.w * u.v3.x);
    r.y = f2tf32(w.x * u.v0.y + w.y * u.v1.y + w.z * u.v2.y + w.w * u.v3.y);
    r.z = f2tf32(w.x * u.v0.z + w.y * u.v1.z + w.z * u.v2.z + w.w * u.v3.z);
    r.w = f2tf32(w.x * u.v0.w + w.y * u.v1.w + w.z * u.v2.w + w.w * u.v3.w);
    *(uint4*)(smem + Ans_off + px * 128 + ((l ^ (px & 7)) * 16)) = r;
}

__global__ __launch_bounds__(256, 1) void dcn_mma_kernel(
    const float* __restrict__ x,      // [8,64,64,256]
    const float* __restrict__ bias,   // [256]
    float* __restrict__ out)          // [32768,256]
{
    extern __shared__ char smem[];
    const uint32_t sb = smem_u32(smem);
    const int tid = threadIdx.x;
    const int lane = tid & 31, wid = tid >> 5;
    const int l = lane & 7, pq = lane >> 3;
    const int wm = wid & 3, wn = wid >> 2;
    const int m0 = (blockIdx.x >> 1) * 256;
    const int f0 = (blockIdx.x & 1) * 128;

    float4* SW0 = (float4*)(smem + SM_SW);
    int4*   SO0 = (int4*)(smem + SM_SO);

    float acc[4][8][4];
    #pragma unroll
    for (int mt = 0; mt < 4; ++mt)
        #pragma unroll
        for (int nt = 0; nt < 8; ++nt)
            #pragma unroll
            for (int q = 0; q < 4; ++q) acc[mt][nt][q] = 0.f;

    // ldmatrix address precompute
    const int rowA = wm * 64 + (lane & 15);
    const int hiA = (lane >> 4) & 1;
    const int rowB = wn * 64 + (lane >> 4) * 8 + (lane & 7);
    uint32_t koffA[4], koffB[4];
    #pragma unroll
    for (int ks = 0; ks < 4; ++ks) {
        koffA[ks] = (uint32_t)((ks * 32 + hiA * 16) ^ ((rowA & 7) * 16));
        koffB[ks] = (uint32_t)((ks * 32 + ((lane >> 3) & 1) * 16) ^ ((lane & 7) * 16));
    }
    const uint32_t rowAoff = (uint32_t)(rowA * 128);
    const uint32_t rowBoff = (uint32_t)(rowB * 128);

    // ---------------- Prologue ----------------
    compute_params3(0, m0 + tid, SW0 + tid, SO0 + tid);
    __syncthreads();
    if (tid < 128) loadB3(sb, f0, 0, 0, tid);
    CP_COMMIT();
    {
        const int cb0 = l * 4;
        #pragma unroll
        for (int it = 0; it < 8; ++it) {
            const int px = wid * 32 + it * 4 + pq;
            GBuf u;
            gather_issue(x, SO0, px, cb0, u);
            combine_sts(smem, SW0, px, l, SM_A, u);
        }
    }
    CP_WAIT0();
    __syncthreads();

    // ---------------- Main loop: consume j, produce j+1 ----------------
    for (int j = 0; j < 71; ++j) {
        const int s = j & 1, ns = s ^ 1;
        const int pb1 = ((j + 1) >> 3) & 1;
        const float4* SWn = SW0 + pb1 * 256;
        const int4*   SOn = SO0 + pb1 * 256;
        const int cb = ((j + 1) & 7) * 32 + l * 4;
        const uint32_t Ans_off = (uint32_t)(SM_A + ns * 32768);

        if (tid < 128) loadB3(sb, f0, j + 1, ns, tid);
        CP_COMMIT();

        const uint32_t Ab = sb + SM_A + s * 32768 + rowAoff;
        const uint32_t Bb = sb + SM_B + s * 16384 + rowBoff;

        GBuf u0, u1;
        int px0 = wid * 32 + pq, px1;
        gather_issue(x, SOn, px0, cb, u0);

        #pragma unroll
        for (int ks = 0; ks < 4; ++ks) {
            uint32_t a[4][4];
            #pragma unroll
            for (int mt = 0; mt < 4; ++mt)
                LDSM4(a[mt], Ab + mt * 2048 + koffA[ks]);

            px1 = wid * 32 + (2 * ks + 1) * 4 + pq;
            gather_issue(x, SOn, px1, cb, u1);

            // MMA half 1: nt 0..3
            {
                uint32_t b0[4], b1[4];
                LDSM4(b0, Bb + 0 * 2048 + koffB[ks]);
                LDSM4(b1, Bb + 1 * 2048 + koffB[ks]);
                #pragma unroll
                for (int mt = 0; mt < 4; ++mt) {
                    mma_tf32(acc[mt][0], a[mt], b0);
                    mma_tf32(acc[mt][1], a[mt], b0 + 2);
                    mma_tf32(acc[mt][2], a[mt], b1);
                    mma_tf32(acc[mt][3], a[mt], b1 + 2);
                }
            }
            combine_sts(smem, SWn, px0, l, Ans_off, u0);
            if (ks < 3) {
                px0 = wid * 32 + (2 * ks + 2) * 4 + pq;
                gather_issue(x, SOn, px0, cb, u0);
            }
            // MMA half 2: nt 4..7
            {
                uint32_t b0[4], b1[4];
                LDSM4(b0, Bb + 2 * 2048 + koffB[ks]);
                LDSM4(b1, Bb + 3 * 2048 + koffB[ks]);
                #pragma unroll
                for (int mt = 0; mt < 4; ++mt) {
                    mma_tf32(acc[mt][4], a[mt], b0);
                    mma_tf32(acc[mt][5], a[mt], b0 + 2);
                    mma_tf32(acc[mt][6], a[mt], b1);
                    mma_tf32(acc[mt][7], a[mt], b1 + 2);
                }
            }
            combine_sts(smem, SWn, px1, l, Ans_off, u1);
        }

        if ((j + 2) < 72 && ((j + 2) & 7) == 0) {
            const int kp = (j + 2) >> 3, pb = kp & 1;
            compute_params3(kp, m0 + tid, SW0 + pb * 256 + tid, SO0 + pb * 256 + tid);
        }
        CP_WAIT0();
        __syncthreads();
    }

    // ---------------- Final consume: chunk 71 (stage 1) ----------------
    {
        const uint32_t Ab = sb + SM_A + 1 * 32768 + rowAoff;
        const uint32_t Bb = sb + SM_B + 1 * 16384 + rowBoff;
        #pragma unroll
        for (int ks = 0; ks < 4; ++ks) {
            uint32_t a[4][4];
            #pragma unroll
            for (int mt = 0; mt < 4; ++mt)
                LDSM4(a[mt], Ab + mt * 2048 + koffA[ks]);
            #pragma unroll
            for (int nh = 0; nh < 2; ++nh) {
                uint32_t b0[4], b1[4];
                LDSM4(b0, Bb + (nh * 2 + 0) * 2048 + koffB[ks]);
                LDSM4(b1, Bb + (nh * 2 + 1) * 2048 + koffB[ks]);
                #pragma unroll
                for (int mt = 0; mt < 4; ++mt) {
                    mma_tf32(acc[mt][nh * 4 + 0], a[mt], b0);
                    mma_tf32(acc[mt][nh * 4 + 1], a[mt], b0 + 2);
                    mma_tf32(acc[mt][nh * 4 + 2], a[mt], b1);
                    mma_tf32(acc[mt][nh * 4 + 3], a[mt], b1 + 2);
                }
            }
        }
    }

    // ---------------- Epilogue: bias + store ----------------
    const int g = lane >> 2, cq = lane & 3;
    #pragma unroll
    for (int nt = 0; nt < 8; ++nt) {
        const int fl = f0 + wn * 64 + nt * 8 + 2 * cq;
        const float2 bv = *(const float2*)(bias + fl);
        #pragma unroll
        for (int mt = 0; mt < 4; ++mt) {
            const int r0 = m0 + wm * 64 + mt * 16 + g;
            float2 v0, v1;
            v0.x = acc[mt][nt][0] + bv.x;
            v0.y = acc[mt][nt][1] + bv.y;
            v1.x = acc[mt][nt][2] + bv.x;
            v1.y = acc[mt][nt][3] + bv.y;
            *(float2*)(out + (size_t)r0 * 256 + fl) = v0;
            *(float2*)(out + (size_t)(r0 + 8) * 256 + fl) = v1;
        }
    }
}

// ============================ Launch ============================
extern "C" void kernel_launch(void* const* d_in, const int* in_sizes, int n_in,
                              void* d_out, int out_size) {
    (void)in_sizes; (void)n_in; (void)out_size;
    const float* x    = (const float*)d_in[0];
    const float* omw  = (const float*)d_in[1];
    const float* omb  = (const float*)d_in[2];
    const float* W    = (const float*)d_in[3];
    const float* bias = (const float*)d_in[4];
    float* out = (float*)d_out;

    static bool attr_set = false;
    if (!attr_set) {
        cudaFuncSetAttribute(dcn_mma_kernel,
                             cudaFuncAttributeMaxDynamicSharedMemorySize, SM_TOTAL);
        attr_set = true;
    }

    transpose_w<<<dim3(KTOT / 32, FF / 32), 256>>>(W);
    om_conv_kernel<<<1024, 256>>>(x, omw, omb);
    dcn_mma_kernel<<<256, 256, SM_TOTAL>>>(x, bias, out);
}

// round 10
// speedup vs baseline: 1.7493x; 1.2305x over previous
#include <cuda_runtime.h>
#include <cuda_fp16.h>
#include <cstdint>
#include <math.h>

// Problem constants (fixed by the dataset)
#define BB 8
#define HH 64
#define WW 64
#define CC 256
#define FF 256
#define NPIX (BB*HH*WW)   // 32768
#define KTOT 2304         // 9*256

__device__ float g_om[NPIX * 27];
__device__ __half g_Wh[FF * KTOT];   // [256][2304]  Wh[f][k] = fp16(W[k][f])

// ============================ helpers ============================
__device__ __forceinline__ uint32_t smem_u32(const void* p) {
    uint32_t a;
    asm("{ .reg .u64 t; cvta.to.shared.u64 t, %1; cvt.u32.u64 %0, t; }"
        : "=r"(a) : "l"(p));
    return a;
}
#define CP_ASYNC16(dst, src) \
    asm volatile("cp.async.cg.shared.global [%0], [%1], 16;" :: "r"(dst), "l"(src) : "memory")
#define CP_COMMIT() asm volatile("cp.async.commit_group;" ::: "memory")
#define CP_WAIT0()  asm volatile("cp.async.wait_group 0;" ::: "memory")

#define LDSM4(r, a) \
    asm volatile("ldmatrix.sync.aligned.m8n8.x4.shared.b16 {%0,%1,%2,%3}, [%4];" \
        : "=r"((r)[0]), "=r"((r)[1]), "=r"((r)[2]), "=r"((r)[3]) : "r"(a))

__device__ __forceinline__ void mma_f16(float* c, const uint32_t* a, const uint32_t* b) {
    asm volatile("mma.sync.aligned.m16n8k16.row.col.f32.f16.f16.f32 "
        "{%0,%1,%2,%3}, {%4,%5,%6,%7}, {%8,%9}, {%0,%1,%2,%3};"
        : "+f"(c[0]), "+f"(c[1]), "+f"(c[2]), "+f"(c[3])
        : "r"(a[0]), "r"(a[1]), "r"(a[2]), "r"(a[3]), "r"(b[0]), "r"(b[1]));
}

// ============================ Kernel 0: W transpose + fp16 =====================
__global__ __launch_bounds__(256) void transpose_w(const float* __restrict__ W) {
    __shared__ float t[32][33];
    int k0 = blockIdx.x * 32, f0 = blockIdx.y * 32;
    int tx = threadIdx.x & 31, ty = threadIdx.x >> 5;
    #pragma unroll
    for (int r = 0; r < 32; r += 8)
        t[ty + r][tx] = W[(k0 + ty + r) * 256 + f0 + tx];
    __syncthreads();
    #pragma unroll
    for (int r = 0; r < 32; r += 8)
        g_Wh[(f0 + ty + r) * KTOT + k0 + tx] = __float2half_rn(t[tx][ty + r]);
}

// ============================ Kernel 1: offset/mask conv (fp32) ==============
__global__ __launch_bounds__(256) void om_conv_kernel(
    const float* __restrict__ x, const float* __restrict__ omw,
    const float* __restrict__ omb)
{
    __shared__ float ws[256 * 32];
    const int bid = blockIdx.x;
    const int xh = bid & 1;
    const int y = (bid >> 1) & 63;
    const int b = bid >> 7;
    const int x0 = xh * 32;
    const int tid = threadIdx.x;
    const int p = tid >> 3;
    const int fg = tid & 7;

    for (int i = tid; i < 256 * 32; i += 256) ws[i] = 0.f;

    float4 acc = make_float4(0.f, 0.f, 0.f, 0.f);
    const int gx = x0 + p;

    for (int tap = 0; tap < 9; ++tap) {
        __syncthreads();
        for (int i = tid; i < 256 * 27; i += 256) {
            int c = i / 27;
            int f = i - c * 27;
            ws[c * 32 + f] = omw[(tap * 256 + c) * 27 + f];
        }
        __syncthreads();
        const int dy = tap / 3;
        const int dx = tap - dy * 3;
        const int sy = y - 1 + dy;
        const int sx = gx - 1 + dx;
        if ((unsigned)sy < 64u && (unsigned)sx < 64u) {
            const float* xr = x + (((b * 64 + sy) * 64) + sx) * 256;
            #pragma unroll 4
            for (int c4 = 0; c4 < 64; ++c4) {
                float4 xv = *(const float4*)(xr + c4 * 4);
                const float* wp = &ws[(c4 * 4) * 32 + fg * 4];
                float4 w0 = *(const float4*)(wp);
                float4 w1 = *(const float4*)(wp + 32);
                float4 w2 = *(const float4*)(wp + 64);
                float4 w3 = *(const float4*)(wp + 96);
                acc.x = fmaf(xv.x, w0.x, acc.x); acc.y = fmaf(xv.x, w0.y, acc.y);
                acc.z = fmaf(xv.x, w0.z, acc.z); acc.w = fmaf(xv.x, w0.w, acc.w);
                acc.x = fmaf(xv.y, w1.x, acc.x); acc.y = fmaf(xv.y, w1.y, acc.y);
                acc.z = fmaf(xv.y, w1.z, acc.z); acc.w = fmaf(xv.y, w1.w, acc.w);
                acc.x = fmaf(xv.z, w2.x, acc.x); acc.y = fmaf(xv.z, w2.y, acc.y);
                acc.z = fmaf(xv.z, w2.z, acc.z); acc.w = fmaf(xv.z, w2.w, acc.w);
                acc.x = fmaf(xv.w, w3.x, acc.x); acc.y = fmaf(xv.w, w3.y, acc.y);
                acc.z = fmaf(xv.w, w3.z, acc.z); acc.w = fmaf(xv.w, w3.w, acc.w);
            }
        }
    }
    const int pix = (b * 64 + y) * 64 + gx;
    float vals[4] = {acc.x, acc.y, acc.z, acc.w};
    #pragma unroll
    for (int ff = 0; ff < 4; ++ff) {
        int f = fg * 4 + ff;
        if (f < 27) {
            float v = vals[ff] + omb[f];
            if (f >= 18) v = 2.f / (1.f + expf(-v));
            g_om[pix * 27 + f] = v;
        }
    }
}

// ============================ Kernel 2: fused sampling + fp16 mma GEMM ========
// CTA: 256 threads (8 warps), tile M=128 x N=256 (full N). Grid 256 m-tiles.
// Warps: 2(m) x 4(n), warp tile 64x64, fp16 m16n8k16, acc[4 mt][8 nt][4] f32.
// 72 K-chunks of 32 fp16; 2 smem stages; gathers for j+1 pipelined through MMA j.
// A rows: 128 x 64B (32 fp16), swizzle granule g' = g ^ ((row>>1)&3).
// B rows: 256 x 64B, same swizzle.
#define SM_SW 0              // [2][128] float4 bilinear weights (4KB)
#define SM_SO 4096           // [2][128] int4 corner offsets (4KB)
#define SM_A  8192           // [2][128][64B] fp16 (16KB)
#define SM_B  24576          // [2][256][64B] fp16 (32KB)
#define SM_TOTAL 57344

__device__ __forceinline__ void compute_params3(int kp, int m, float4* sw4, int4* so4) {
    const float* omp = g_om + m * 27;
    const int y = (m >> 6) & 63, xc = m & 63, b = m >> 12;
    const int ky = kp / 3, kx = kp - ky * 3;
    float py = (float)(y - 1 + ky) + omp[2 * kp];
    float px = (float)(xc - 1 + kx) + omp[2 * kp + 1];
    float msk = omp[18 + kp];
    float y0f = floorf(py), x0f = floorf(px);
    float wy1 = py - y0f, wy0 = 1.f - wy1;
    float wx1 = px - x0f, wx0 = 1.f - wx1;
    int iy0 = (int)y0f, ix0 = (int)x0f;
    int iy1 = iy0 + 1, ix1 = ix0 + 1;
    bool vy0 = (unsigned)iy0 < 64u, vy1 = (unsigned)iy1 < 64u;
    bool vx0 = (unsigned)ix0 < 64u, vx1 = (unsigned)ix1 < 64u;
    int cy0 = min(max(iy0, 0), 63), cy1 = min(max(iy1, 0), 63);
    int cx0 = min(max(ix0, 0), 63), cx1 = min(max(ix1, 0), 63);
    int base = b << 12;
    int4 o;
    o.x = (base + cy0 * 64 + cx0) << 8;
    o.y = (base + cy0 * 64 + cx1) << 8;
    o.z = (base + cy1 * 64 + cx0) << 8;
    o.w = (base + cy1 * 64 + cx1) << 8;
    float4 w;
    w.x = (vy0 && vx0) ? wy0 * wx0 * msk : 0.f;
    w.y = (vy0 && vx1) ? wy0 * wx1 * msk : 0.f;
    w.z = (vy1 && vx0) ? wy1 * wx0 * msk : 0.f;
    w.w = (vy1 && vx1) ? wy1 * wx1 * msk : 0.f;
    *so4 = o;
    *sw4 = w;
}

// Stage B chunk j: 256 n-rows x 32 fp16 (64B), swizzled; all 256 threads.
__device__ __forceinline__ void loadB3(uint32_t sb, int j, int stage, int n) {
    const uint32_t dbase = sb + SM_B + stage * 16384 + n * 64;
    const int ssel = (n >> 1) & 3;
    const __half* src = g_Wh + (size_t)n * KTOT + j * 32;
    #pragma unroll
    for (int g = 0; g < 4; ++g)
        CP_ASYNC16(dbase + ((g ^ ssel) * 16), src + g * 8);
}

struct GBuf { float4 v0, v1, v2, v3; };

__device__ __forceinline__ void gather_issue(const float* __restrict__ x,
                                             const int4* SOn, int px, int cb,
                                             GBuf& u) {
    const int4 o = SOn[px];
    u.v0 = *(const float4*)(x + o.x + cb);
    u.v1 = *(const float4*)(x + o.y + cb);
    u.v2 = *(const float4*)(x + o.z + cb);
    u.v3 = *(const float4*)(x + o.w + cb);
}

// Combine 4 corners -> 4 floats -> 4 fp16, store 8B into swizzled A row.
__device__ __forceinline__ void combine_sts(char* smem, const float4* SWn,
                                            int px, int l, uint32_t Ans_off,
                                            const GBuf& u) {
    const float4 w = SWn[px];
    float c0 = w.x * u.v0.x + w.y * u.v1.x + w.z * u.v2.x + w.w * u.v3.x;
    float c1 = w.x * u.v0.y + w.y * u.v1.y + w.z * u.v2.y + w.w * u.v3.y;
    float c2 = w.x * u.v0.z + w.y * u.v1.z + w.z * u.v2.z + w.w * u.v3.z;
    float c3 = w.x * u.v0.w + w.y * u.v1.w + w.z * u.v2.w + w.w * u.v3.w;
    __half2 p0 = __floats2half2_rn(c0, c1);
    __half2 p1 = __floats2half2_rn(c2, c3);
    uint2 st;
    st.x = *(const uint32_t*)&p0;
    st.y = *(const uint32_t*)&p1;
    const uint32_t off = Ans_off + (uint32_t)(px * 64 +
        (((l >> 1) ^ ((px >> 1) & 3)) * 16) + (l & 1) * 8);
    *(uint2*)(smem + off) = st;
}

__global__ __launch_bounds__(256, 1) void dcn_mma_kernel(
    const float* __restrict__ x,      // [8,64,64,256]
    const float* __restrict__ bias,   // [256]
    float* __restrict__ out)          // [32768,256]
{
    extern __shared__ char smem[];
    const uint32_t sb = smem_u32(smem);
    const int tid = threadIdx.x;
    const int lane = tid & 31, wid = tid >> 5;
    const int l = lane & 7, pq = lane >> 3;
    const int wm = wid & 1, wn = wid >> 1;     // 2m x 4n
    const int m0 = blockIdx.x * 128;

    float4* SW0 = (float4*)(smem + SM_SW);
    int4*   SO0 = (int4*)(smem + SM_SO);

    float acc[4][8][4];
    #pragma unroll
    for (int mt = 0; mt < 4; ++mt)
        #pragma unroll
        for (int nt = 0; nt < 8; ++nt)
            #pragma unroll
            for (int q = 0; q < 4; ++q) acc[mt][nt][q] = 0.f;

    // ldmatrix lane->address precompute
    // A: tiles (m0-7,kLo),(m8-15,kLo),(m0-7,kHi),(m8-15,kHi)
    const int rA = wm * 64 + (lane & 7) + ((lane >> 3) & 1) * 8;
    const int kbitA = lane >> 4;
    // B: tiles (n0-7,kLo),(n0-7,kHi),(n8-15,kLo),(n8-15,kHi)
    const int rB = wn * 64 + (lane & 7) + (lane >> 4) * 8;
    const int kbitB = (lane >> 3) & 1;
    uint32_t koffA[2], koffB[2];
    #pragma unroll
    for (int ks = 0; ks < 2; ++ks) {
        koffA[ks] = (uint32_t)(((ks * 2 + kbitA) ^ ((rA >> 1) & 3)) * 16);
        koffB[ks] = (uint32_t)(((ks * 2 + kbitB) ^ ((rB >> 1) & 3)) * 16);
    }
    const uint32_t rowAoff = (uint32_t)(rA * 64);
    const uint32_t rowBoff = (uint32_t)(rB * 64);

    // ---------------- Prologue ----------------
    if (tid < 128) compute_params3(0, m0 + tid, SW0 + tid, SO0 + tid);
    __syncthreads();
    loadB3(sb, 0, 0, tid);
    CP_COMMIT();
    {
        const int cb0 = l * 4;
        #pragma unroll
        for (int p = 0; p < 4; ++p) {
            const int px = wid * 16 + p * 4 + pq;
            GBuf u;
            gather_issue(x, SO0, px, cb0, u);
            combine_sts(smem, SW0, px, l, SM_A, u);
        }
    }
    CP_WAIT0();
    __syncthreads();

    // ---------------- Main loop: consume j, produce j+1 ----------------
    for (int j = 0; j < 71; ++j) {
        const int s = j & 1, ns = s ^ 1;
        const int pb1 = ((j + 1) >> 3) & 1;
        const float4* SWn = SW0 + pb1 * 128;
        const int4*   SOn = SO0 + pb1 * 128;
        const int cb = ((j + 1) & 7) * 32 + l * 4;
        const uint32_t Ans_off = (uint32_t)(SM_A + ns * 8192);
        const int pxb = wid * 16 + pq;

        loadB3(sb, j + 1, ns, tid);
        CP_COMMIT();

        const uint32_t Ab = sb + SM_A + s * 8192 + rowAoff;
        const uint32_t Bb = sb + SM_B + s * 16384 + rowBoff;

        GBuf u0, u1, u2, u3;
        gather_issue(x, SOn, pxb + 0, cb, u0);
        gather_issue(x, SOn, pxb + 4, cb, u1);

        #pragma unroll
        for (int ks = 0; ks < 2; ++ks) {
            uint32_t a[4][4];
            #pragma unroll
            for (int mt = 0; mt < 4; ++mt)
                LDSM4(a[mt], Ab + mt * 1024 + koffA[ks]);

            if (ks == 0) gather_issue(x, SOn, pxb + 8, cb, u2);

            // B ntp 0,1 then MMA
            {
                uint32_t b0[4], b1[4];
                LDSM4(b0, Bb + 0 * 1024 + koffB[ks]);
                LDSM4(b1, Bb + 1 * 1024 + koffB[ks]);
                #pragma unroll
                for (int mt = 0; mt < 4; ++mt) {
                    mma_f16(acc[mt][0], a[mt], b0);
                    mma_f16(acc[mt][1], a[mt], b0 + 2);
                    mma_f16(acc[mt][2], a[mt], b1);
                    mma_f16(acc[mt][3], a[mt], b1 + 2);
                }
            }
            if (ks == 0) combine_sts(smem, SWn, pxb + 0, l, Ans_off, u0);
            else         combine_sts(smem, SWn, pxb + 8, l, Ans_off, u2);
            if (ks == 0) gather_issue(x, SOn, pxb + 12, cb, u3);
            // B ntp 2,3 then MMA
            {
                uint32_t b0[4], b1[4];
                LDSM4(b0, Bb + 2 * 1024 + koffB[ks]);
                LDSM4(b1, Bb + 3 * 1024 + koffB[ks]);
                #pragma unroll
                for (int mt = 0; mt < 4; ++mt) {
                    mma_f16(acc[mt][4], a[mt], b0);
                    mma_f16(acc[mt][5], a[mt], b0 + 2);
                    mma_f16(acc[mt][6], a[mt], b1);
                    mma_f16(acc[mt][7], a[mt], b1 + 2);
                }
            }
            if (ks == 0) combine_sts(smem, SWn, pxb + 4, l, Ans_off, u1);
            else         combine_sts(smem, SWn, pxb + 12, l, Ans_off, u3);
        }

        if ((j + 2) < 72 && ((j + 2) & 7) == 0 && tid < 128) {
            const int kp = (j + 2) >> 3, pb = kp & 1;
            compute_params3(kp, m0 + tid, SW0 + pb * 128 + tid, SO0 + pb * 128 + tid);
        }
        CP_WAIT0();
        __syncthreads();
    }

    // ---------------- Final consume: chunk 71 (stage 1) ----------------
    {
        const uint32_t Ab = sb + SM_A + 1 * 8192 + rowAoff;
        const uint32_t Bb = sb + SM_B + 1 * 16384 + rowBoff;
        #pragma unroll
        for (int ks = 0; ks < 2; ++ks) {
            uint32_t a[4][4];
            #pragma unroll
            for (int mt = 0; mt < 4; ++mt)
                LDSM4(a[mt], Ab + mt * 1024 + koffA[ks]);
            #pragma unroll
            for (int np = 0; np < 4; ++np) {
                uint32_t b[4];
                LDSM4(b, Bb + np * 1024 + koffB[ks]);
                #pragma unroll
                for (int mt = 0; mt < 4; ++mt) {
                    mma_f16(acc[mt][np * 2 + 0], a[mt], b);
                    mma_f16(acc[mt][np * 2 + 1], a[mt], b + 2);
                }
            }
        }
    }

    // ---------------- Epilogue: bias + store ----------------
    // nt -> n: ntp = nt>>1 block of 16, +8 if odd nt. fl = wn*64 + (nt>>1)*16 + (nt&1)*8 + 2cq
    const int g = lane >> 2, cq = lane & 3;
    #pragma unroll
    for (int nt = 0; nt < 8; ++nt) {
        const int fl = wn * 64 + (nt >> 1) * 16 + (nt & 1) * 8 + 2 * cq;
        const float2 bv = *(const float2*)(bias + fl);
        #pragma unroll
        for (int mt = 0; mt < 4; ++mt) {
            const int r0 = m0 + wm * 64 + mt * 16 + g;
            float2 v0, v1;
            v0.x = acc[mt][nt][0] + bv.x;
            v0.y = acc[mt][nt][1] + bv.y;
            v1.x = acc[mt][nt][2] + bv.x;
            v1.y = acc[mt][nt][3] + bv.y;
            *(float2*)(out + (size_t)r0 * 256 + fl) = v0;
            *(float2*)(out + (size_t)(r0 + 8) * 256 + fl) = v1;
        }
    }
}

// ============================ Launch ============================
extern "C" void kernel_launch(void* const* d_in, const int* in_sizes, int n_in,
                              void* d_out, int out_size) {
    (void)in_sizes; (void)n_in; (void)out_size;
    const float* x    = (const float*)d_in[0];
    const float* omw  = (const float*)d_in[1];
    const float* omb  = (const float*)d_in[2];
    const float* W    = (const float*)d_in[3];
    const float* bias = (const float*)d_in[4];
    float* out = (float*)d_out;

    static bool attr_set = false;
    if (!attr_set) {
        cudaFuncSetAttribute(dcn_mma_kernel,
                             cudaFuncAttributeMaxDynamicSharedMemorySize, SM_TOTAL);
        attr_set = true;
    }

    transpose_w<<<dim3(KTOT / 32, FF / 32), 256>>>(W);
    om_conv_kernel<<<1024, 256>>>(x, omw, omb);
    dcn_mma_kernel<<<256, 256, SM_TOTAL>>>(x, bias, out);
}

// round 12
// speedup vs baseline: 3.7863x; 2.1645x over previous
#include <cuda_runtime.h>
#include <cuda_fp16.h>
#include <cstdint>
#include <math.h>

// Problem constants (fixed by the dataset)
#define BB 8
#define HH 64
#define WW 64
#define CC 256
#define FF 256
#define NPIX (BB*HH*WW)   // 32768
#define KTOT 2304         // 9*256

__device__ float g_om[NPIX * 27];
__device__ __half g_Wh[FF * KTOT];     // main weights transposed: Wh[f][k]
__device__ __half g_OMWh[32 * KTOT];   // om weights: OMWh[f][tap*256+c], f 27..31 = 0

// ============================ helpers ============================
__device__ __forceinline__ uint32_t smem_u32(const void* p) {
    uint32_t a;
    asm("{ .reg .u64 t; cvta.to.shared.u64 t, %1; cvt.u32.u64 %0, t; }"
        : "=r"(a) : "l"(p));
    return a;
}
#define CP_ASYNC16(dst, src) \
    asm volatile("cp.async.cg.shared.global [%0], [%1], 16;" :: "r"(dst), "l"(src) : "memory")
#define CP_COMMIT() asm volatile("cp.async.commit_group;" ::: "memory")
#define CP_WAIT0()  asm volatile("cp.async.wait_group 0;" ::: "memory")

#define LDSM4(r, a) \
    asm volatile("ldmatrix.sync.aligned.m8n8.x4.shared.b16 {%0,%1,%2,%3}, [%4];" \
        : "=r"((r)[0]), "=r"((r)[1]), "=r"((r)[2]), "=r"((r)[3]) : "r"(a))

__device__ __forceinline__ void mma_f16(float* c, const uint32_t* a, const uint32_t* b) {
    asm volatile("mma.sync.aligned.m16n8k16.row.col.f32.f16.f16.f32 "
        "{%0,%1,%2,%3}, {%4,%5,%6,%7}, {%8,%9}, {%0,%1,%2,%3};"
        : "+f"(c[0]), "+f"(c[1]), "+f"(c[2]), "+f"(c[3])
        : "r"(a[0]), "r"(a[1]), "r"(a[2]), "r"(a[3]), "r"(b[0]), "r"(b[1]));
}

// ============================ Kernel 0a: main W transpose + fp16 ==============
__global__ __launch_bounds__(256) void transpose_w(const float* __restrict__ W) {
    __shared__ float t[32][33];
    int k0 = blockIdx.x * 32, f0 = blockIdx.y * 32;
    int tx = threadIdx.x & 31, ty = threadIdx.x >> 5;
    #pragma unroll
    for (int r = 0; r < 32; r += 8)
        t[ty + r][tx] = W[(k0 + ty + r) * 256 + f0 + tx];
    __syncthreads();
    #pragma unroll
    for (int r = 0; r < 32; r += 8)
        g_Wh[(f0 + ty + r) * KTOT + k0 + tx] = __float2half_rn(t[tx][ty + r]);
}

// ============================ Kernel 0b: om W prep (27->32 pad, fp16) =========
__global__ __launch_bounds__(256) void om_prep_w(const float* __restrict__ omw) {
    int k = blockIdx.x * 256 + threadIdx.x;   // 0..2303
    if (k < KTOT) {
        #pragma unroll
        for (int f = 0; f < 32; ++f) {
            float v = (f < 27) ? omw[k * 27 + f] : 0.f;
            g_OMWh[f * KTOT + k] = __float2half_rn(v);
        }
    }
}

// ============================ Kernel 1: om conv via fp16 mma ==================
// M=128 pixels/CTA (grid 256), N=32 (27 used), K=2304 in 72 chunks of 32.
// 256 threads / 8 warps, warp tile 16x32 (m-split 8). acc[4 nt][4].
// A rows: 128 x 64B fp16 (shifted input rows, zero-padded at borders).
// B rows: 32 x 64B fp16. Same 16B-granule swizzle as the main kernel.
__global__ __launch_bounds__(256, 1) void om_mma_kernel(
    const float* __restrict__ x,      // [8,64,64,256]
    const float* __restrict__ omb)    // [27]
{
    __shared__ __align__(16) char smem[2 * 8192 + 2 * 2048];   // A 16KB + B 4KB
    const uint32_t sb = smem_u32(smem);
    const uint32_t A_OFF = 0, B_OFF = 16384;
    const int tid = threadIdx.x;
    const int lane = tid & 31, wid = tid >> 5;
    const int m0 = blockIdx.x * 128;

    float acc[4][4];
    #pragma unroll
    for (int nt = 0; nt < 4; ++nt)
        #pragma unroll
        for (int q = 0; q < 4; ++q) acc[nt][q] = 0.f;

    // ldmatrix addressing
    const int rA = wid * 16 + (lane & 7) + ((lane >> 3) & 1) * 8;
    const int kbitA = lane >> 4;
    const int rB = (lane & 7) + (lane >> 4) * 8;
    const int kbitB = (lane >> 3) & 1;
    uint32_t koffA[2], koffB[2];
    #pragma unroll
    for (int ks = 0; ks < 2; ++ks) {
        koffA[ks] = (uint32_t)(((ks * 2 + kbitA) ^ ((rA >> 1) & 3)) * 16);
        koffB[ks] = (uint32_t)(((ks * 2 + kbitB) ^ ((rB >> 1) & 3)) * 16);
    }
    const uint32_t rowAoff = (uint32_t)(rA * 64);
    const uint32_t rowBoff = (uint32_t)(rB * 64);

    // per-thread A staging identity: px row, 16 channels (half)
    const int px = tid >> 1, half = tid & 1;
    const int m = m0 + px;
    const int y = (m >> 6) & 63, xc = m & 63, b = m >> 12;

    // stage lambda-ish macros
    auto stageA = [&](int j, int stage) {
        const int tap = j >> 3;
        const int ky = tap / 3, kx = tap - ky * 3;
        const int sy = y - 1 + ky, sx = xc - 1 + kx;
        const bool valid = ((unsigned)sy < 64u) && ((unsigned)sx < 64u);
        float4 va = {0,0,0,0}, vb = {0,0,0,0}, vc = {0,0,0,0}, vd = {0,0,0,0};
        if (valid) {
            const float* src = x + (((b << 12) + sy * 64 + sx) << 8)
                               + (j & 7) * 32 + half * 16;
            va = *(const float4*)(src);
            vb = *(const float4*)(src + 4);
            vc = *(const float4*)(src + 8);
            vd = *(const float4*)(src + 12);
        }
        __half2 h0 = __floats2half2_rn(va.x, va.y);
        __half2 h1 = __floats2half2_rn(va.z, va.w);
        __half2 h2 = __floats2half2_rn(vb.x, vb.y);
        __half2 h3 = __floats2half2_rn(vb.z, vb.w);
        __half2 h4 = __floats2half2_rn(vc.x, vc.y);
        __half2 h5 = __floats2half2_rn(vc.z, vc.w);
        __half2 h6 = __floats2half2_rn(vd.x, vd.y);
        __half2 h7 = __floats2half2_rn(vd.z, vd.w);
        uint4 s0, s1;
        s0.x = *(uint32_t*)&h0; s0.y = *(uint32_t*)&h1;
        s0.z = *(uint32_t*)&h2; s0.w = *(uint32_t*)&h3;
        s1.x = *(uint32_t*)&h4; s1.y = *(uint32_t*)&h5;
        s1.z = *(uint32_t*)&h6; s1.w = *(uint32_t*)&h7;
        const int g0 = half * 2, ss = (px >> 1) & 3;
        char* base = smem + A_OFF + stage * 8192 + px * 64;
        *(uint4*)(base + ((g0 ^ ss) * 16)) = s0;
        *(uint4*)(base + (((g0 + 1) ^ ss) * 16)) = s1;
    };
    auto stageB = [&](int j, int stage) {
        if (tid < 128) {
            const int n = tid >> 2, g = tid & 3;
            const uint32_t dst = sb + B_OFF + stage * 2048 + n * 64
                                 + ((g ^ ((n >> 1) & 3)) * 16);
            CP_ASYNC16(dst, g_OMWh + (size_t)n * KTOT + j * 32 + g * 8);
        }
    };

    // prologue
    stageB(0, 0);
    CP_COMMIT();
    stageA(0, 0);
    CP_WAIT0();
    __syncthreads();

    for (int j = 0; j < 72; ++j) {
        const int s = j & 1, ns = s ^ 1;
        if (j < 71) {
            stageB(j + 1, ns);
            CP_COMMIT();
            stageA(j + 1, ns);
        }
        const uint32_t Ab = sb + A_OFF + s * 8192 + rowAoff;
        const uint32_t Bb = sb + B_OFF + s * 2048 + rowBoff;
        #pragma unroll
        for (int ks = 0; ks < 2; ++ks) {
            uint32_t a[4];
            LDSM4(a, Ab + koffA[ks]);
            uint32_t b0[4], b1[4];
            LDSM4(b0, Bb + 0 * 1024 + koffB[ks]);
            LDSM4(b1, Bb + 1 * 1024 + koffB[ks]);
            mma_f16(acc[0], a, b0);
            mma_f16(acc[1], a, b0 + 2);
            mma_f16(acc[2], a, b1);
            mma_f16(acc[3], a, b1 + 2);
        }
        if (j < 71) CP_WAIT0();
        __syncthreads();
    }

    // epilogue: bias, sigmoid for mask channels, scatter to g_om
    const int g = lane >> 2, cq = lane & 3;
    #pragma unroll
    for (int nt = 0; nt < 4; ++nt) {
        #pragma unroll
        for (int q = 0; q < 4; ++q) {
            const int f = nt * 8 + 2 * cq + (q & 1);
            if (f < 27) {
                const int row = m0 + wid * 16 + g + ((q >> 1) * 8);
                float v = acc[nt][q] + omb[f];
                if (f >= 18) v = 2.f / (1.f + expf(-v));
                g_om[row * 27 + f] = v;
            }
        }
    }
}

// ============================ Kernel 2: fused sampling + fp16 mma GEMM ========
// CTA: 512 threads (16 warps), tile M=128 x N=256. Grid 256 m-tiles.
// Warps: 4(m) x 4(n), warp tile 32x64, fp16 m16n8k16, acc[2 mt][8 nt][4] f32.
// 72 K-chunks of 32 fp16; 2 smem stages; gathers for j+1 pipelined through MMA j.
#define SM_SW 0              // [2][128] float4 bilinear weights (4KB)
#define SM_SO 4096           // [2][128] int4 corner offsets (4KB)
#define SM_A  8192           // [2][128][64B] fp16 (16KB)
#define SM_B  24576          // [2][256][64B] fp16 (32KB)
#define SM_TOTAL 57344

__device__ __forceinline__ void compute_params3(int kp, int m, float4* sw4, int4* so4) {
    const float* omp = g_om + m * 27;
    const int y = (m >> 6) & 63, xc = m & 63, b = m >> 12;
    const int ky = kp / 3, kx = kp - ky * 3;
    float py = (float)(y - 1 + ky) + omp[2 * kp];
    float px = (float)(xc - 1 + kx) + omp[2 * kp + 1];
    float msk = omp[18 + kp];
    float y0f = floorf(py), x0f = floorf(px);
    float wy1 = py - y0f, wy0 = 1.f - wy1;
    float wx1 = px - x0f, wx0 = 1.f - wx1;
    int iy0 = (int)y0f, ix0 = (int)x0f;
    int iy1 = iy0 + 1, ix1 = ix0 + 1;
    bool vy0 = (unsigned)iy0 < 64u, vy1 = (unsigned)iy1 < 64u;
    bool vx0 = (unsigned)ix0 < 64u, vx1 = (unsigned)ix1 < 64u;
    int cy0 = min(max(iy0, 0), 63), cy1 = min(max(iy1, 0), 63);
    int cx0 = min(max(ix0, 0), 63), cx1 = min(max(ix1, 0), 63);
    int base = b << 12;
    int4 o;
    o.x = (base + cy0 * 64 + cx0) << 8;
    o.y = (base + cy0 * 64 + cx1) << 8;
    o.z = (base + cy1 * 64 + cx0) << 8;
    o.w = (base + cy1 * 64 + cx1) << 8;
    float4 w;
    w.x = (vy0 && vx0) ? wy0 * wx0 * msk : 0.f;
    w.y = (vy0 && vx1) ? wy0 * wx1 * msk : 0.f;
    w.z = (vy1 && vx0) ? wy1 * wx0 * msk : 0.f;
    w.w = (vy1 && vx1) ? wy1 * wx1 * msk : 0.f;
    *so4 = o;
    *sw4 = w;
}

// Stage B chunk j with 512 threads: n = tid>>1, two 16B granules each.
__device__ __forceinline__ void loadB3(uint32_t sb, int j, int stage, int tid) {
    const int n = tid >> 1, g0 = (tid & 1) * 2;
    const int ss = (n >> 1) & 3;
    const uint32_t dbase = sb + SM_B + stage * 16384 + n * 64;
    const __half* src = g_Wh + (size_t)n * KTOT + j * 32;
    CP_ASYNC16(dbase + ((g0 ^ ss) * 16), src + g0 * 8);
    CP_ASYNC16(dbase + (((g0 + 1) ^ ss) * 16), src + (g0 + 1) * 8);
}

__global__ __launch_bounds__(512, 1) void dcn_mma_kernel(
    const float* __restrict__ x,      // [8,64,64,256]
    const float* __restrict__ bias,   // [256]
    float* __restrict__ out)          // [32768,256]
{
    extern __shared__ char smem[];
    const uint32_t sb = smem_u32(smem);
    const int tid = threadIdx.x;
    const int lane = tid & 31, wid = tid >> 5;
    const int wm = wid & 3, wn = wid >> 2;     // 4m x 4n
    const int m0 = blockIdx.x * 128;

    float4* SW0 = (float4*)(smem + SM_SW);
    int4*   SO0 = (int4*)(smem + SM_SO);

    float acc[2][8][4];
    #pragma unroll
    for (int mt = 0; mt < 2; ++mt)
        #pragma unroll
        for (int nt = 0; nt < 8; ++nt)
            #pragma unroll
            for (int q = 0; q < 4; ++q) acc[mt][nt][q] = 0.f;

    // ldmatrix addressing
    const int rA = wm * 32 + (lane & 7) + ((lane >> 3) & 1) * 8;
    const int kbitA = lane >> 4;
    const int rB = wn * 64 + (lane & 7) + (lane >> 4) * 8;
    const int kbitB = (lane >> 3) & 1;
    uint32_t koffA[2], koffB[2];
    #pragma unroll
    for (int ks = 0; ks < 2; ++ks) {
        koffA[ks] = (uint32_t)(((ks * 2 + kbitA) ^ ((rA >> 1) & 3)) * 16);
        koffB[ks] = (uint32_t)(((ks * 2 + kbitB) ^ ((rB >> 1) & 3)) * 16);
    }
    const uint32_t rowAoff = (uint32_t)(rA * 64);
    const uint32_t rowBoff = (uint32_t)(rB * 64);

    // sampling identity: 4 threads per pixel, thread owns 8 channels
    const int spx = tid >> 2, sq = tid & 3;
    const uint32_t stsoff = (uint32_t)(spx * 64 + ((sq ^ ((spx >> 1) & 3)) * 16));

    // ---------------- Prologue ----------------
    if (tid < 128) compute_params3(0, m0 + tid, SW0 + tid, SO0 + tid);
    __syncthreads();
    loadB3(sb, 0, 0, tid);
    CP_COMMIT();
    {
        const int cb = sq * 8;
        const int4 o = SO0[spx];
        const float4 w = SW0[spx];
        float4 v0a = *(const float4*)(x + o.x + cb), v0b = *(const float4*)(x + o.x + cb + 4);
        float4 v1a = *(const float4*)(x + o.y + cb), v1b = *(const float4*)(x + o.y + cb + 4);
        float4 v2a = *(const float4*)(x + o.z + cb), v2b = *(const float4*)(x + o.z + cb + 4);
        float4 v3a = *(const float4*)(x + o.w + cb), v3b = *(const float4*)(x + o.w + cb + 4);
        float c[8];
        c[0] = w.x*v0a.x + w.y*v1a.x + w.z*v2a.x + w.w*v3a.x;
        c[1] = w.x*v0a.y + w.y*v1a.y + w.z*v2a.y + w.w*v3a.y;
        c[2] = w.x*v0a.z + w.y*v1a.z + w.z*v2a.z + w.w*v3a.z;
        c[3] = w.x*v0a.w + w.y*v1a.w + w.z*v2a.w + w.w*v3a.w;
        c[4] = w.x*v0b.x + w.y*v1b.x + w.z*v2b.x + w.w*v3b.x;
        c[5] = w.x*v0b.y + w.y*v1b.y + w.z*v2b.y + w.w*v3b.y;
        c[6] = w.x*v0b.z + w.y*v1b.z + w.z*v2b.z + w.w*v3b.z;
        c[7] = w.x*v0b.w + w.y*v1b.w + w.z*v2b.w + w.w*v3b.w;
        __half2 h0 = __floats2half2_rn(c[0], c[1]);
        __half2 h1 = __floats2half2_rn(c[2], c[3]);
        __half2 h2 = __floats2half2_rn(c[4], c[5]);
        __half2 h3 = __floats2half2_rn(c[6], c[7]);
        uint4 st;
        st.x = *(uint32_t*)&h0; st.y = *(uint32_t*)&h1;
        st.z = *(uint32_t*)&h2; st.w = *(uint32_t*)&h3;
        *(uint4*)(smem + SM_A + stsoff) = st;
    }
    CP_WAIT0();
    __syncthreads();

    // ---------------- Main loop: consume j, produce j+1 ----------------
    for (int j = 0; j < 71; ++j) {
        const int s = j & 1, ns = s ^ 1;
        const int pb1 = ((j + 1) >> 3) & 1;
        const float4* SWn = SW0 + pb1 * 128;
        const int4*   SOn = SO0 + pb1 * 128;
        const int cb = ((j + 1) & 7) * 32 + sq * 8;
        const uint32_t Ans = (uint32_t)(SM_A + ns * 8192);

        loadB3(sb, j + 1, ns, tid);
        CP_COMMIT();

        const uint32_t Ab = sb + SM_A + s * 8192 + rowAoff;
        const uint32_t Bb = sb + SM_B + s * 16384 + rowBoff;

        const int4 o = SOn[spx];
        const float4 w = SWn[spx];

        // gather corners 0,1
        float4 v0a = *(const float4*)(x + o.x + cb), v0b = *(const float4*)(x + o.x + cb + 4);
        float4 v1a = *(const float4*)(x + o.y + cb), v1b = *(const float4*)(x + o.y + cb + 4);

        // ks0: A + B np0/1, acc nt0..3
        uint32_t a0[2][4];
        LDSM4(a0[0], Ab + 0 * 1024 + koffA[0]);
        LDSM4(a0[1], Ab + 1 * 1024 + koffA[0]);
        {
            uint32_t b0[4], b1[4];
            LDSM4(b0, Bb + 0 * 1024 + koffB[0]);
            LDSM4(b1, Bb + 1 * 1024 + koffB[0]);
            #pragma unroll
            for (int mt = 0; mt < 2; ++mt) {
                mma_f16(acc[mt][0], a0[mt], b0);
                mma_f16(acc[mt][1], a0[mt], b0 + 2);
                mma_f16(acc[mt][2], a0[mt], b1);
                mma_f16(acc[mt][3], a0[mt], b1 + 2);
            }
        }
        // partial combine with corners 0,1
        float c[8];
        c[0] = w.x*v0a.x + w.y*v1a.x;
        c[1] = w.x*v0a.y + w.y*v1a.y;
        c[2] = w.x*v0a.z + w.y*v1a.z;
        c[3] = w.x*v0a.w + w.y*v1a.w;
        c[4] = w.x*v0b.x + w.y*v1b.x;
        c[5] = w.x*v0b.y + w.y*v1b.y;
        c[6] = w.x*v0b.z + w.y*v1b.z;
        c[7] = w.x*v0b.w + w.y*v1b.w;
        // gather corners 2,3
        float4 v2a = *(const float4*)(x + o.z + cb), v2b = *(const float4*)(x + o.z + cb + 4);
        float4 v3a = *(const float4*)(x + o.w + cb), v3b = *(const float4*)(x + o.w + cb + 4);

        // ks0: B np2/3, acc nt4..7
        {
            uint32_t b0[4], b1[4];
            LDSM4(b0, Bb + 2 * 1024 + koffB[0]);
            LDSM4(b1, Bb + 3 * 1024 + koffB[0]);
            #pragma unroll
            for (int mt = 0; mt < 2; ++mt) {
                mma_f16(acc[mt][4], a0[mt], b0);
                mma_f16(acc[mt][5], a0[mt], b0 + 2);
                mma_f16(acc[mt][6], a0[mt], b1);
                mma_f16(acc[mt][7], a0[mt], b1 + 2);
            }
        }
        // finish combine + STS
        c[0] += w.z*v2a.x + w.w*v3a.x;
        c[1] += w.z*v2a.y + w.w*v3a.y;
        c[2] += w.z*v2a.z + w.w*v3a.z;
        c[3] += w.z*v2a.w + w.w*v3a.w;
        c[4] += w.z*v2b.x + w.w*v3b.x;
        c[5] += w.z*v2b.y + w.w*v3b.y;
        c[6] += w.z*v2b.z + w.w*v3b.z;
        c[7] += w.z*v2b.w + w.w*v3b.w;
        {
            __half2 h0 = __floats2half2_rn(c[0], c[1]);
            __half2 h1 = __floats2half2_rn(c[2], c[3]);
            __half2 h2 = __floats2half2_rn(c[4], c[5]);
            __half2 h3 = __floats2half2_rn(c[6], c[7]);
            uint4 st;
            st.x = *(uint32_t*)&h0; st.y = *(uint32_t*)&h1;
            st.z = *(uint32_t*)&h2; st.w = *(uint32_t*)&h3;
            *(uint4*)(smem + Ans + stsoff) = st;
        }
        // ks1: full block
        {
            uint32_t a1[2][4];
            LDSM4(a1[0], Ab + 0 * 1024 + koffA[1]);
            LDSM4(a1[1], Ab + 1 * 1024 + koffA[1]);
            #pragma unroll
            for (int np = 0; np < 4; ++np) {
                uint32_t b[4];
                LDSM4(b, Bb + np * 1024 + koffB[1]);
                #pragma unroll
                for (int mt = 0; mt < 2; ++mt) {
                    mma_f16(acc[mt][np * 2 + 0], a1[mt], b);
                    mma_f16(acc[mt][np * 2 + 1], a1[mt], b + 2);
                }
            }
        }

        if ((j + 2) < 72 && ((j + 2) & 7) == 0 && tid < 128) {
            const int kp = (j + 2) >> 3, pb = kp & 1;
            compute_params3(kp, m0 + tid, SW0 + pb * 128 + tid, SO0 + pb * 128 + tid);
        }
        CP_WAIT0();
        __syncthreads();
    }

    // ---------------- Final consume: chunk 71 (stage 1) ----------------
    {
        const uint32_t Ab = sb + SM_A + 1 * 8192 + rowAoff;
        const uint32_t Bb = sb + SM_B + 1 * 16384 + rowBoff;
        #pragma unroll
        for (int ks = 0; ks < 2; ++ks) {
            uint32_t a[2][4];
            LDSM4(a[0], Ab + 0 * 1024 + koffA[ks]);
            LDSM4(a[1], Ab + 1 * 1024 + koffA[ks]);
            #pragma unroll
            for (int np = 0; np < 4; ++np) {
                uint32_t b[4];
                LDSM4(b, Bb + np * 1024 + koffB[ks]);
                #pragma unroll
                for (int mt = 0; mt < 2; ++mt) {
                    mma_f16(acc[mt][np * 2 + 0], a[mt], b);
                    mma_f16(acc[mt][np * 2 + 1], a[mt], b + 2);
                }
            }
        }
    }

    // ---------------- Epilogue: bias + store ----------------
    const int g = lane >> 2, cq = lane & 3;
    #pragma unroll
    for (int nt = 0; nt < 8; ++nt) {
        const int fl = wn * 64 + (nt >> 1) * 16 + (nt & 1) * 8 + 2 * cq;
        const float2 bv = *(const float2*)(bias + fl);
        #pragma unroll
        for (int mt = 0; mt < 2; ++mt) {
            const int r0 = m0 + wm * 32 + mt * 16 + g;
            float2 v0, v1;
            v0.x = acc[mt][nt][0] + bv.x;
            v0.y = acc[mt][nt][1] + bv.y;
            v1.x = acc[mt][nt][2] + bv.x;
            v1.y = acc[mt][nt][3] + bv.y;
            *(float2*)(out + (size_t)r0 * 256 + fl) = v0;
            *(float2*)(out + (size_t)(r0 + 8) * 256 + fl) = v1;
        }
    }
}

// ============================ Launch ============================
extern "C" void kernel_launch(void* const* d_in, const int* in_sizes, int n_in,
                              void* d_out, int out_size) {
    (void)in_sizes; (void)n_in; (void)out_size;
    const float* x    = (const float*)d_in[0];
    const float* omw  = (const float*)d_in[1];
    const float* omb  = (const float*)d_in[2];
    const float* W    = (const float*)d_in[3];
    const float* bias = (const float*)d_in[4];
    float* out = (float*)d_out;

    static bool attr_set = false;
    if (!attr_set) {
        cudaFuncSetAttribute(dcn_mma_kernel,
                             cudaFuncAttributeMaxDynamicSharedMemorySize, SM_TOTAL);
        attr_set = true;
    }

    transpose_w<<<dim3(KTOT / 32, FF / 32), 256>>>(W);
    om_prep_w<<<9, 256>>>(omw);
    om_mma_kernel<<<256, 256>>>(x, omb);
    dcn_mma_kernel<<<256, 512, SM_TOTAL>>>(x, bias, out);
}